// round 3
// baseline (speedup 1.0000x reference)
#include <cuda_runtime.h>
#include <cstdint>

#define C      128
#define C4     32
#define GMAX   64
#define LNUM   3
#define NCAP   100000
#define ECAP   1000000
#define NEG    0.01f
#define EPSV   1e-5f
#define SCANB  1024
#define NBMAX  128

typedef unsigned long long ull;

// ---------------- static scratch ----------------
__device__ float g_xw  [(size_t)NCAP * C];   // (x @ W) * dinv[row]
__device__ float g_agg [(size_t)NCAP * C];   // post-aggregation (GCN output)
__device__ int   g_degi[NCAP];
__device__ float g_dinv[NCAP];
__device__ float g_cnt   [GMAX];
__device__ float g_cntinv[GMAX];
__device__ float g_ssum[GMAX * C];
__device__ float g_ssq [GMAX * C];
__device__ float g_A   [GMAX * C];
__device__ float g_B   [GMAX * C];
// CSR by dst
__device__ int g_off [NCAP + 1];
__device__ int g_fill[NCAP];
__device__ int g_esrc[ECAP];
__device__ int g_bsum[NBMAX];

__device__ __forceinline__ ull pack2(float a, float b) {
    ull r; asm("mov.b64 %0, {%1, %2};" : "=l"(r) : "f"(a), "f"(b)); return r;
}
__device__ __forceinline__ float2 unpack(ull p) {
    float2 r; asm("mov.b64 {%0, %1}, %2;" : "=f"(r.x), "=f"(r.y) : "l"(p)); return r;
}

// ---------------- prep ----------------
__global__ void k_zero_prep(int N) {
    int i = blockIdx.x * blockDim.x + threadIdx.x;
    if (i < N)    { g_degi[i] = 0; g_fill[i] = 0; }
    if (i < GMAX) g_cnt[i] = 0.f;
}

__global__ void k_count(const int* __restrict__ ei, const int* __restrict__ batch,
                        int E, int N) {
    int i = blockIdx.x * blockDim.x + threadIdx.x;
    if (i < E) atomicAdd(&g_degi[ei[E + i]], 1);
    if (i < N) atomicAdd(&g_cnt[batch[i]], 1.0f);
}

__global__ void k_finprep(int N) {
    int i = blockIdx.x * blockDim.x + threadIdx.x;
    if (i < N)    g_dinv[i]   = rsqrtf((float)g_degi[i] + 1.0f);
    if (i < GMAX) g_cntinv[i] = 1.0f / fmaxf(g_cnt[i], 1.0f);
}

// ---------------- prefix scan over degrees -> CSR offsets ----------------
__global__ void k_scan1(int N) {
    __shared__ int red[SCANB];
    int tid = threadIdx.x;
    int i = blockIdx.x * SCANB + tid;
    red[tid] = (i < N) ? g_degi[i] : 0;
    __syncthreads();
#pragma unroll
    for (int s = SCANB / 2; s > 0; s >>= 1) {
        if (tid < s) red[tid] += red[tid + s];
        __syncthreads();
    }
    if (tid == 0) g_bsum[blockIdx.x] = red[0];
}

__global__ void k_scan2(int nb) {
    __shared__ int sb[NBMAX];
    int tid = threadIdx.x;
    int v = (tid < nb) ? g_bsum[tid] : 0;
    sb[tid] = v;
    __syncthreads();
#pragma unroll
    for (int off = 1; off < NBMAX; off <<= 1) {
        int t = (tid >= off) ? sb[tid - off] : 0;
        __syncthreads();
        sb[tid] += t;
        __syncthreads();
    }
    if (tid < nb) g_bsum[tid] = sb[tid] - v;   // exclusive
}

__global__ void k_scan3(int N, int E) {
    __shared__ int s[SCANB];
    int tid = threadIdx.x;
    int i = blockIdx.x * SCANB + tid;
    int v = (i < N) ? g_degi[i] : 0;
    s[tid] = v;
    __syncthreads();
#pragma unroll
    for (int off = 1; off < SCANB; off <<= 1) {
        int t = (tid >= off) ? s[tid - off] : 0;
        __syncthreads();
        s[tid] += t;
        __syncthreads();
    }
    if (i < N) g_off[i] = s[tid] - v + g_bsum[blockIdx.x];
    if (i == 0) g_off[N] = E;
}

__global__ void k_bucket(const int* __restrict__ ei, int E) {
    int i = blockIdx.x * blockDim.x + threadIdx.x;
    if (i >= E) return;
    int src = ei[i], d = ei[E + i];
    int pos = g_off[d] + atomicAdd(&g_fill[d], 1);
    g_esrc[pos] = src;
}

// ---------------- GEMM: g_xw = (X @ W) * dinv ----------------
// k-pair packing: fma.rn.f32x2 accumulates even-k in .lo, odd-k in .hi.
// Block 256, tile 64 rows x 128 cols. Thread: 4 rows x 8 cols.
__global__ void __launch_bounds__(256, 2)
k_gemm(const float* __restrict__ X, const float* __restrict__ W, int N) {
    extern __shared__ char smraw[];
    ull* Xp = (ull*)smraw;                       // [64][64] k-pairs: 32KB
    ull* Wp = (ull*)(smraw + 64 * 64 * 8);       // [64 kp][128 c]:   64KB

    int tid  = threadIdx.x;
    int row0 = blockIdx.x * 64;

    // pack W: Wp[kp*128+c] = (W[2kp][c], W[2kp+1][c])
#pragma unroll
    for (int i = 0; i < 32; i++) {
        int idx = tid + 256 * i;                 // 0..8191
        int kp = idx >> 7, c = idx & 127;
        float a = W[(size_t)(2 * kp) * C + c];
        float b = W[(size_t)(2 * kp + 1) * C + c];
        Wp[idx] = pack2(a, b);
    }
    // X tile: natural k-adjacent pairs
    const float4* X4 = (const float4*)X;
#pragma unroll
    for (int i = 0; i < 8; i++) {
        int idx = tid + 256 * i;                 // 0..2047
        int r = idx >> 5, c4 = idx & 31;
        int n = row0 + r;
        float4 v = (n < N) ? X4[(size_t)n * C4 + c4] : make_float4(0.f, 0.f, 0.f, 0.f);
        ulonglong2 p; p.x = pack2(v.x, v.y); p.y = pack2(v.z, v.w);
        *(ulonglong2*)(Xp + (size_t)r * 64 + c4 * 2) = p;
    }
    __syncthreads();

    int tx = tid & 15, ty = tid >> 4;
    int c0 = tx * 8;

    ull acc[4][8];
#pragma unroll
    for (int i = 0; i < 4; i++)
#pragma unroll
        for (int j = 0; j < 8; j++) acc[i][j] = 0ull;

#pragma unroll 2
    for (int kp = 0; kp < 64; kp++) {
        ull xv[4];
#pragma unroll
        for (int i = 0; i < 4; i++) xv[i] = Xp[(size_t)(ty * 4 + i) * 64 + kp];
        const ulonglong2* wr = (const ulonglong2*)(Wp + (size_t)kp * 128 + c0);
        ulonglong2 w0 = wr[0], w1 = wr[1], w2 = wr[2], w3 = wr[3];
#pragma unroll
        for (int i = 0; i < 4; i++) {
            asm("fma.rn.f32x2 %0, %1, %2, %0;" : "+l"(acc[i][0]) : "l"(xv[i]), "l"(w0.x));
            asm("fma.rn.f32x2 %0, %1, %2, %0;" : "+l"(acc[i][1]) : "l"(xv[i]), "l"(w0.y));
            asm("fma.rn.f32x2 %0, %1, %2, %0;" : "+l"(acc[i][2]) : "l"(xv[i]), "l"(w1.x));
            asm("fma.rn.f32x2 %0, %1, %2, %0;" : "+l"(acc[i][3]) : "l"(xv[i]), "l"(w1.y));
            asm("fma.rn.f32x2 %0, %1, %2, %0;" : "+l"(acc[i][4]) : "l"(xv[i]), "l"(w2.x));
            asm("fma.rn.f32x2 %0, %1, %2, %0;" : "+l"(acc[i][5]) : "l"(xv[i]), "l"(w2.y));
            asm("fma.rn.f32x2 %0, %1, %2, %0;" : "+l"(acc[i][6]) : "l"(xv[i]), "l"(w3.x));
            asm("fma.rn.f32x2 %0, %1, %2, %0;" : "+l"(acc[i][7]) : "l"(xv[i]), "l"(w3.y));
        }
    }

#pragma unroll
    for (int i = 0; i < 4; i++) {
        int n = row0 + ty * 4 + i;
        if (n >= N) continue;
        float di = g_dinv[n];
        float o[8];
#pragma unroll
        for (int j = 0; j < 8; j++) {
            float2 p = unpack(acc[i][j]);
            o[j] = (p.x + p.y) * di;
        }
        *(float4*)(g_xw + (size_t)n * C + c0)     = make_float4(o[0], o[1], o[2], o[3]);
        *(float4*)(g_xw + (size_t)n * C + c0 + 4) = make_float4(o[4], o[5], o[6], o[7]);
    }
}

// ---------------- CSR gather: g_agg[n] = (sum_in g_xw[s] + g_xw[n]) * dinv[n] + b --------
__global__ void k_gather(const float* __restrict__ bias, int N) {
    int n = (blockIdx.x * 256 + threadIdx.x) >> 5;
    if (n >= N) return;
    int lane = threadIdx.x & 31;
    const float4* xw4 = (const float4*)g_xw;

    int beg = g_off[n], end = g_off[n + 1];
    float4 a0 = make_float4(0.f, 0.f, 0.f, 0.f), a1 = a0, a2 = a0, a3 = a0;

    for (int j = beg; j < end; j += 32) {
        int myi = j + lane;
        int sidx = (myi < end) ? g_esrc[myi] : 0;
        int cnt = min(32, end - j);
        int t = 0;
        for (; t + 4 <= cnt; t += 4) {
            int s0 = __shfl_sync(0xffffffffu, sidx, t);
            int s1 = __shfl_sync(0xffffffffu, sidx, t + 1);
            int s2 = __shfl_sync(0xffffffffu, sidx, t + 2);
            int s3 = __shfl_sync(0xffffffffu, sidx, t + 3);
            float4 v0 = xw4[(size_t)s0 * C4 + lane];
            float4 v1 = xw4[(size_t)s1 * C4 + lane];
            float4 v2 = xw4[(size_t)s2 * C4 + lane];
            float4 v3 = xw4[(size_t)s3 * C4 + lane];
            a0.x += v0.x; a0.y += v0.y; a0.z += v0.z; a0.w += v0.w;
            a1.x += v1.x; a1.y += v1.y; a1.z += v1.z; a1.w += v1.w;
            a2.x += v2.x; a2.y += v2.y; a2.z += v2.z; a2.w += v2.w;
            a3.x += v3.x; a3.y += v3.y; a3.z += v3.z; a3.w += v3.w;
        }
        for (; t < cnt; t++) {
            int sv = __shfl_sync(0xffffffffu, sidx, t);
            float4 v = xw4[(size_t)sv * C4 + lane];
            a0.x += v.x; a0.y += v.y; a0.z += v.z; a0.w += v.w;
        }
    }

    float di = g_dinv[n];
    float4 self = xw4[(size_t)n * C4 + lane];
    float4 b = ((const float4*)bias)[lane];
    float4 r;
    r.x = fmaf(a0.x + a1.x + a2.x + a3.x + self.x, di, b.x);
    r.y = fmaf(a0.y + a1.y + a2.y + a3.y + self.y, di, b.y);
    r.z = fmaf(a0.z + a1.z + a2.z + a3.z + self.z, di, b.z);
    r.w = fmaf(a0.w + a1.w + a2.w + a3.w + self.w, di, b.w);
    ((float4*)g_agg)[(size_t)n * C4 + lane] = r;
}

// ---------------- GraphNorm statistics ----------------
__global__ void k_zero_stats() {
    int i = blockIdx.x * blockDim.x + threadIdx.x;
    if (i < GMAX * C) { g_ssum[i] = 0.f; g_ssq[i] = 0.f; }
}

__global__ void k_reduce(const int* __restrict__ batch, int N) {
    __shared__ int bs[256];
    int c  = threadIdx.x;
    int n0 = blockIdx.x * 256;
    for (int i = c; i < 256; i += 128) {
        int n = n0 + i;
        bs[i] = (n < N) ? batch[n] : -1;
    }
    __syncthreads();
    int lim = N - n0; if (lim > 256) lim = 256;
    if (lim <= 0) return;
    float s = 0.f, q = 0.f;
    int gcur = bs[0];
    for (int i = 0; i < lim; i++) {
        int g = bs[i];
        if (g != gcur) {
            atomicAdd(&g_ssum[gcur * C + c], s);
            atomicAdd(&g_ssq [gcur * C + c], q);
            s = 0.f; q = 0.f; gcur = g;
        }
        float v = g_agg[(size_t)(n0 + i) * C + c];
        s += v;
        q = fmaf(v, v, q);
    }
    atomicAdd(&g_ssum[gcur * C + c], s);
    atomicAdd(&g_ssq [gcur * C + c], q);
}

__global__ void k_stats(const float* __restrict__ gnw, const float* __restrict__ gnb,
                        const float* __restrict__ gms) {
    int i = blockIdx.x * blockDim.x + threadIdx.x;
    if (i >= GMAX * C) return;
    int g = i >> 7, c = i & (C - 1);
    float ci  = g_cntinv[g];
    float mu  = g_ssum[i] * ci;
    float m2  = g_ssq [i] * ci;
    float sc  = gms[c];
    float var = m2 - mu * mu * (2.f * sc - sc * sc);
    float rstd = rsqrtf(var + EPSV);
    float A = rstd * gnw[c];
    g_A[i] = A;
    g_B[i] = gnb[c] - mu * sc * A;
}

// ---------------- norm + leaky relu + history ----------------
__global__ void k_norm(const int* __restrict__ batch, float* __restrict__ hist,
                       float* __restrict__ fin, int N) {
    int t = blockIdx.x * blockDim.x + threadIdx.x;
    int n = t >> 5;
    if (n >= N) return;
    int c4 = t & 31;
    int g = batch[n];
    float4 v = ((const float4*)g_agg)[(size_t)n * C4 + c4];
    float4 a = ((const float4*)g_A)[g * C4 + c4];
    float4 b = ((const float4*)g_B)[g * C4 + c4];
    float4 y;
    y.x = fmaf(v.x, a.x, b.x); y.x = fmaxf(y.x, NEG * y.x);
    y.y = fmaf(v.y, a.y, b.y); y.y = fmaxf(y.y, NEG * y.y);
    y.z = fmaf(v.z, a.z, b.z); y.z = fmaxf(y.z, NEG * y.z);
    y.w = fmaf(v.w, a.w, b.w); y.w = fmaxf(y.w, NEG * y.w);
    ((float4*)hist)[(size_t)n * C4 + c4] = y;
    if (fin) ((float4*)fin)[(size_t)n * C4 + c4] = y;
}

// ---------------- launch ----------------
extern "C" void kernel_launch(void* const* d_in, const int* in_sizes, int n_in,
                              void* d_out, int out_size) {
    const float* x     = (const float*)d_in[0];
    const int*   ei    = (const int*)d_in[1];
    const int*   batch = (const int*)d_in[2];
    const float* W     = (const float*)d_in[3];
    const float* b     = (const float*)d_in[4];
    const float* gnw   = (const float*)d_in[5];
    const float* gnb   = (const float*)d_in[6];
    const float* gms   = (const float*)d_in[7];
    float* out = (float*)d_out;

    int N = in_sizes[0] / C;
    int E = in_sizes[1] / 2;
    size_t NC = (size_t)N * C;

    const int GEMM_SMEM = 64 * 64 * 8 + 64 * 128 * 8;   // 96 KB
    cudaFuncSetAttribute(k_gemm, cudaFuncAttributeMaxDynamicSharedMemorySize,
                         GEMM_SMEM);

    int zb = (N + 255) / 256;
    k_zero_prep<<<zb, 256>>>(N);
    int cm = (E > N ? E : N);
    k_count<<<(cm + 255) / 256, 256>>>(ei, batch, E, N);
    k_finprep<<<zb, 256>>>(N);

    int nb = (N + SCANB - 1) / SCANB;
    k_scan1<<<nb, SCANB>>>(N);
    k_scan2<<<1, NBMAX>>>(nb);
    k_scan3<<<nb, SCANB>>>(N, E);
    k_bucket<<<(E + 255) / 256, 256>>>(ei, E);

    const float* xin = x;
    for (int l = 0; l < LNUM; l++) {
        k_gemm<<<(N + 63) / 64, 256, GEMM_SMEM>>>(xin, W + (size_t)l * C * C, N);
        k_zero_stats<<<(GMAX * C + 255) / 256, 256>>>();
        k_gather<<<(N * 32 + 255) / 256, 256>>>(b + (size_t)l * C, N);
        k_reduce<<<(N + 255) / 256, 128>>>(batch, N);
        k_stats<<<(GMAX * C + 255) / 256, 256>>>(gnw + (size_t)l * C,
                                                 gnb + (size_t)l * C,
                                                 gms + (size_t)l * C);
        float* hist = out + NC * (size_t)(1 + l);
        float* fin  = (l == LNUM - 1) ? out : nullptr;
        k_norm<<<((size_t)N * 32 + 255) / 256, 256>>>(batch, hist, fin, N);
        xin = hist;
    }
}

// round 4
// speedup vs baseline: 1.0118x; 1.0118x over previous
#include <cuda_runtime.h>
#include <cstdint>

#define C      128
#define C4     32
#define GMAX   64
#define LNUM   3
#define NCAP   100000
#define ECAP   1000000
#define NEG    0.01f
#define EPSV   1e-5f
#define SCANB  1024
#define NBMAX  128

typedef unsigned long long ull;

// ---------------- static scratch ----------------
__device__ float g_xw  [(size_t)NCAP * C];   // (x @ W) * dinv[row]
__device__ float g_agg [(size_t)NCAP * C];   // post-aggregation (GCN output)
__device__ int   g_degi[NCAP];
__device__ float g_dinv[NCAP];
__device__ float g_cnt   [GMAX];
__device__ float g_cntinv[GMAX];
__device__ float g_ssum[GMAX * C];
__device__ float g_ssq [GMAX * C];
__device__ float g_A   [GMAX * C];
__device__ float g_B   [GMAX * C];
// CSR by dst
__device__ int g_off [NCAP + 1];
__device__ int g_fill[NCAP];
__device__ int g_esrc[ECAP];
__device__ int g_bsum[NBMAX];

__device__ __forceinline__ ull pack2(float a, float b) {
    ull r; asm("mov.b64 %0, {%1, %2};" : "=l"(r) : "f"(a), "f"(b)); return r;
}
__device__ __forceinline__ float2 unpack(ull p) {
    float2 r; asm("mov.b64 {%0, %1}, %2;" : "=f"(r.x), "=f"(r.y) : "l"(p)); return r;
}

// ---------------- prep ----------------
__global__ void k_zero_prep(int N) {
    int i = blockIdx.x * blockDim.x + threadIdx.x;
    if (i < N)    { g_degi[i] = 0; g_fill[i] = 0; }
    if (i < GMAX) g_cnt[i] = 0.f;
}

__global__ void k_count(const int* __restrict__ ei, const int* __restrict__ batch,
                        int E, int N) {
    int i = blockIdx.x * blockDim.x + threadIdx.x;
    if (i < E) atomicAdd(&g_degi[ei[E + i]], 1);
    if (i < N) atomicAdd(&g_cnt[batch[i]], 1.0f);
}

__global__ void k_finprep(int N) {
    int i = blockIdx.x * blockDim.x + threadIdx.x;
    if (i < N)    g_dinv[i]   = rsqrtf((float)g_degi[i] + 1.0f);
    if (i < GMAX) g_cntinv[i] = 1.0f / fmaxf(g_cnt[i], 1.0f);
}

// ---------------- prefix scan over degrees -> CSR offsets ----------------
__global__ void k_scan1(int N) {
    __shared__ int red[SCANB];
    int tid = threadIdx.x;
    int i = blockIdx.x * SCANB + tid;
    red[tid] = (i < N) ? g_degi[i] : 0;
    __syncthreads();
#pragma unroll
    for (int s = SCANB / 2; s > 0; s >>= 1) {
        if (tid < s) red[tid] += red[tid + s];
        __syncthreads();
    }
    if (tid == 0) g_bsum[blockIdx.x] = red[0];
}

__global__ void k_scan2(int nb) {
    __shared__ int sb[NBMAX];
    int tid = threadIdx.x;
    int v = (tid < nb) ? g_bsum[tid] : 0;
    sb[tid] = v;
    __syncthreads();
#pragma unroll
    for (int off = 1; off < NBMAX; off <<= 1) {
        int t = (tid >= off) ? sb[tid - off] : 0;
        __syncthreads();
        sb[tid] += t;
        __syncthreads();
    }
    if (tid < nb) g_bsum[tid] = sb[tid] - v;   // exclusive
}

__global__ void k_scan3(int N, int E) {
    __shared__ int s[SCANB];
    int tid = threadIdx.x;
    int i = blockIdx.x * SCANB + tid;
    int v = (i < N) ? g_degi[i] : 0;
    s[tid] = v;
    __syncthreads();
#pragma unroll
    for (int off = 1; off < SCANB; off <<= 1) {
        int t = (tid >= off) ? s[tid - off] : 0;
        __syncthreads();
        s[tid] += t;
        __syncthreads();
    }
    if (i < N) g_off[i] = s[tid] - v + g_bsum[blockIdx.x];
    if (i == 0) g_off[N] = E;
}

__global__ void k_bucket(const int* __restrict__ ei, int E) {
    int i = blockIdx.x * blockDim.x + threadIdx.x;
    if (i >= E) return;
    int src = ei[i], d = ei[E + i];
    int pos = g_off[d] + atomicAdd(&g_fill[d], 1);
    g_esrc[pos] = src;
}

// ---------------- GEMM: g_xw = (X @ W) * dinv ----------------
// k-pair packed fma.rn.f32x2, register double-buffered across kp to hide
// LDS latency. Block 256, tile 64 rows x 128 cols; thread: 4 rows x 8 cols.
__global__ void __launch_bounds__(256, 2)
k_gemm(const float* __restrict__ X, const float* __restrict__ W, int N) {
    extern __shared__ char smraw[];
    ull* Xp = (ull*)smraw;                       // [64 rows][64 kp]: 32KB
    ull* Wp = (ull*)(smraw + 64 * 64 * 8);       // [64 kp][128 c]:   64KB

    int tid  = threadIdx.x;
    int row0 = blockIdx.x * 64;

    // pack W: Wp[kp*128+c] = (W[2kp][c], W[2kp+1][c])
#pragma unroll
    for (int i = 0; i < 32; i++) {
        int idx = tid + 256 * i;
        int kp = idx >> 7, c = idx & 127;
        Wp[idx] = pack2(W[(size_t)(2 * kp) * C + c], W[(size_t)(2 * kp + 1) * C + c]);
    }
    const float4* X4 = (const float4*)X;
#pragma unroll
    for (int i = 0; i < 8; i++) {
        int idx = tid + 256 * i;
        int r = idx >> 5, c4 = idx & 31;
        int n = row0 + r;
        float4 v = (n < N) ? X4[(size_t)n * C4 + c4] : make_float4(0.f, 0.f, 0.f, 0.f);
        ulonglong2 p; p.x = pack2(v.x, v.y); p.y = pack2(v.z, v.w);
        *(ulonglong2*)(Xp + (size_t)r * 64 + c4 * 2) = p;
    }
    __syncthreads();

    int tx = tid & 15, ty = tid >> 4;
    int c0 = tx * 8;
    const ull* xb = Xp + (size_t)(ty * 4) * 64;

    ull acc[4][8];
#pragma unroll
    for (int i = 0; i < 4; i++)
#pragma unroll
        for (int j = 0; j < 8; j++) acc[i][j] = 0ull;

    ull xv[2][4];
    ulonglong2 wv[2][4];
    {
        const ulonglong2* wr = (const ulonglong2*)(Wp + c0);
#pragma unroll
        for (int i = 0; i < 4; i++) xv[0][i] = xb[(size_t)i * 64];
#pragma unroll
        for (int j = 0; j < 4; j++) wv[0][j] = wr[j];
    }

#pragma unroll 2
    for (int kp = 0; kp < 64; kp++) {
        int cur = kp & 1, nxt = cur ^ 1;
        if (kp < 63) {
            const ulonglong2* wr = (const ulonglong2*)(Wp + (size_t)(kp + 1) * 128 + c0);
#pragma unroll
            for (int i = 0; i < 4; i++) xv[nxt][i] = xb[(size_t)i * 64 + kp + 1];
#pragma unroll
            for (int j = 0; j < 4; j++) wv[nxt][j] = wr[j];
        }
#pragma unroll
        for (int i = 0; i < 4; i++) {
            ull xp = xv[cur][i];
            asm("fma.rn.f32x2 %0, %1, %2, %0;" : "+l"(acc[i][0]) : "l"(xp), "l"(wv[cur][0].x));
            asm("fma.rn.f32x2 %0, %1, %2, %0;" : "+l"(acc[i][1]) : "l"(xp), "l"(wv[cur][0].y));
            asm("fma.rn.f32x2 %0, %1, %2, %0;" : "+l"(acc[i][2]) : "l"(xp), "l"(wv[cur][1].x));
            asm("fma.rn.f32x2 %0, %1, %2, %0;" : "+l"(acc[i][3]) : "l"(xp), "l"(wv[cur][1].y));
            asm("fma.rn.f32x2 %0, %1, %2, %0;" : "+l"(acc[i][4]) : "l"(xp), "l"(wv[cur][2].x));
            asm("fma.rn.f32x2 %0, %1, %2, %0;" : "+l"(acc[i][5]) : "l"(xp), "l"(wv[cur][2].y));
            asm("fma.rn.f32x2 %0, %1, %2, %0;" : "+l"(acc[i][6]) : "l"(xp), "l"(wv[cur][3].x));
            asm("fma.rn.f32x2 %0, %1, %2, %0;" : "+l"(acc[i][7]) : "l"(xp), "l"(wv[cur][3].y));
        }
    }

#pragma unroll
    for (int i = 0; i < 4; i++) {
        int n = row0 + ty * 4 + i;
        if (n >= N) continue;
        float di = g_dinv[n];
        float o[8];
#pragma unroll
        for (int j = 0; j < 8; j++) {
            float2 p = unpack(acc[i][j]);
            o[j] = (p.x + p.y) * di;
        }
        *(float4*)(g_xw + (size_t)n * C + c0)     = make_float4(o[0], o[1], o[2], o[3]);
        *(float4*)(g_xw + (size_t)n * C + c0 + 4) = make_float4(o[4], o[5], o[6], o[7]);
    }
}

// ---------------- CSR gather (warp/node, uniform broadcast idx loads) ----------
__global__ void k_gather(const float* __restrict__ bias, int N) {
    int n = (blockIdx.x * 256 + threadIdx.x) >> 5;
    if (n >= N) return;
    int lane = threadIdx.x & 31;
    const float4* xw4 = (const float4*)g_xw;

    int beg = g_off[n], end = g_off[n + 1];
    float4 a0 = make_float4(0.f, 0.f, 0.f, 0.f), a1 = a0, a2 = a0, a3 = a0;

    int j = beg;
    for (; j + 4 <= end; j += 4) {
        int s0 = __ldg(&g_esrc[j]);
        int s1 = __ldg(&g_esrc[j + 1]);
        int s2 = __ldg(&g_esrc[j + 2]);
        int s3 = __ldg(&g_esrc[j + 3]);
        float4 v0 = xw4[(size_t)s0 * C4 + lane];
        float4 v1 = xw4[(size_t)s1 * C4 + lane];
        float4 v2 = xw4[(size_t)s2 * C4 + lane];
        float4 v3 = xw4[(size_t)s3 * C4 + lane];
        a0.x += v0.x; a0.y += v0.y; a0.z += v0.z; a0.w += v0.w;
        a1.x += v1.x; a1.y += v1.y; a1.z += v1.z; a1.w += v1.w;
        a2.x += v2.x; a2.y += v2.y; a2.z += v2.z; a2.w += v2.w;
        a3.x += v3.x; a3.y += v3.y; a3.z += v3.z; a3.w += v3.w;
    }
    for (; j < end; j++) {
        int s = __ldg(&g_esrc[j]);
        float4 v = xw4[(size_t)s * C4 + lane];
        a0.x += v.x; a0.y += v.y; a0.z += v.z; a0.w += v.w;
    }

    float di = g_dinv[n];
    float4 self = xw4[(size_t)n * C4 + lane];
    float4 b = ((const float4*)bias)[lane];
    float4 r;
    r.x = fmaf(a0.x + a1.x + a2.x + a3.x + self.x, di, b.x);
    r.y = fmaf(a0.y + a1.y + a2.y + a3.y + self.y, di, b.y);
    r.z = fmaf(a0.z + a1.z + a2.z + a3.z + self.z, di, b.z);
    r.w = fmaf(a0.w + a1.w + a2.w + a3.w + self.w, di, b.w);
    ((float4*)g_agg)[(size_t)n * C4 + lane] = r;
}

// ---------------- GraphNorm statistics ----------------
__global__ void k_zero_stats() {
    int i = blockIdx.x * blockDim.x + threadIdx.x;
    if (i < GMAX * C) { g_ssum[i] = 0.f; g_ssq[i] = 0.f; }
}

__global__ void k_reduce(const int* __restrict__ batch, int N) {
    __shared__ int bs[256];
    int c  = threadIdx.x;
    int n0 = blockIdx.x * 256;
    for (int i = c; i < 256; i += 128) {
        int n = n0 + i;
        bs[i] = (n < N) ? batch[n] : -1;
    }
    __syncthreads();
    int lim = N - n0; if (lim > 256) lim = 256;
    if (lim <= 0) return;
    float s = 0.f, q = 0.f;
    int gcur = bs[0];
    for (int i = 0; i < lim; i++) {
        int g = bs[i];
        if (g != gcur) {
            atomicAdd(&g_ssum[gcur * C + c], s);
            atomicAdd(&g_ssq [gcur * C + c], q);
            s = 0.f; q = 0.f; gcur = g;
        }
        float v = g_agg[(size_t)(n0 + i) * C + c];
        s += v;
        q = fmaf(v, v, q);
    }
    atomicAdd(&g_ssum[gcur * C + c], s);
    atomicAdd(&g_ssq [gcur * C + c], q);
}

__global__ void k_stats(const float* __restrict__ gnw, const float* __restrict__ gnb,
                        const float* __restrict__ gms) {
    int i = blockIdx.x * blockDim.x + threadIdx.x;
    if (i >= GMAX * C) return;
    int g = i >> 7, c = i & (C - 1);
    float ci  = g_cntinv[g];
    float mu  = g_ssum[i] * ci;
    float m2  = g_ssq [i] * ci;
    float sc  = gms[c];
    float var = m2 - mu * mu * (2.f * sc - sc * sc);
    float rstd = rsqrtf(var + EPSV);
    float A = rstd * gnw[c];
    g_A[i] = A;
    g_B[i] = gnb[c] - mu * sc * A;
}

// ---------------- norm + leaky relu + history ----------------
__global__ void k_norm(const int* __restrict__ batch, float* __restrict__ hist,
                       float* __restrict__ fin, int N) {
    int t = blockIdx.x * blockDim.x + threadIdx.x;
    int n = t >> 5;
    if (n >= N) return;
    int c4 = t & 31;
    int g = batch[n];
    float4 v = ((const float4*)g_agg)[(size_t)n * C4 + c4];
    float4 a = ((const float4*)g_A)[g * C4 + c4];
    float4 b = ((const float4*)g_B)[g * C4 + c4];
    float4 y;
    y.x = fmaf(v.x, a.x, b.x); y.x = fmaxf(y.x, NEG * y.x);
    y.y = fmaf(v.y, a.y, b.y); y.y = fmaxf(y.y, NEG * y.y);
    y.z = fmaf(v.z, a.z, b.z); y.z = fmaxf(y.z, NEG * y.z);
    y.w = fmaf(v.w, a.w, b.w); y.w = fmaxf(y.w, NEG * y.w);
    ((float4*)hist)[(size_t)n * C4 + c4] = y;
    if (fin) ((float4*)fin)[(size_t)n * C4 + c4] = y;
}

// ---------------- launch ----------------
extern "C" void kernel_launch(void* const* d_in, const int* in_sizes, int n_in,
                              void* d_out, int out_size) {
    const float* x     = (const float*)d_in[0];
    const int*   ei    = (const int*)d_in[1];
    const int*   batch = (const int*)d_in[2];
    const float* W     = (const float*)d_in[3];
    const float* b     = (const float*)d_in[4];
    const float* gnw   = (const float*)d_in[5];
    const float* gnb   = (const float*)d_in[6];
    const float* gms   = (const float*)d_in[7];
    float* out = (float*)d_out;

    int N = in_sizes[0] / C;
    int E = in_sizes[1] / 2;
    size_t NC = (size_t)N * C;

    const int GEMM_SMEM = 64 * 64 * 8 + 64 * 128 * 8;   // 96 KB
    cudaFuncSetAttribute(k_gemm, cudaFuncAttributeMaxDynamicSharedMemorySize,
                         GEMM_SMEM);

    int zb = (N + 255) / 256;
    int nb = (N + SCANB - 1) / SCANB;
    // Order chosen so ncu's "-s 5 -c 1" lands on k_gemm (launch index 5).
    k_zero_prep<<<zb, 256>>>(N);                                    // 0
    int cm = (E > N ? E : N);
    k_count<<<(cm + 255) / 256, 256>>>(ei, batch, E, N);            // 1
    k_finprep<<<zb, 256>>>(N);                                      // 2
    k_scan1<<<nb, SCANB>>>(N);                                      // 3
    k_scan2<<<1, NBMAX>>>(nb);                                      // 4
    k_gemm<<<(N + 63) / 64, 256, GEMM_SMEM>>>(x, W, N);             // 5 <- profiled
    k_scan3<<<nb, SCANB>>>(N, E);                                   // 6
    k_bucket<<<(E + 255) / 256, 256>>>(ei, E);                      // 7

    const float* xin = x;
    for (int l = 0; l < LNUM; l++) {
        if (l > 0)
            k_gemm<<<(N + 63) / 64, 256, GEMM_SMEM>>>(xin, W + (size_t)l * C * C, N);
        k_zero_stats<<<(GMAX * C + 255) / 256, 256>>>();
        k_gather<<<(N * 32 + 255) / 256, 256>>>(b + (size_t)l * C, N);
        k_reduce<<<(N + 255) / 256, 128>>>(batch, N);
        k_stats<<<(GMAX * C + 255) / 256, 256>>>(gnw + (size_t)l * C,
                                                 gnb + (size_t)l * C,
                                                 gms + (size_t)l * C);
        float* hist = out + NC * (size_t)(1 + l);
        float* fin  = (l == LNUM - 1) ? out : nullptr;
        k_norm<<<((size_t)N * 32 + 255) / 256, 256>>>(batch, hist, fin, N);
        xin = hist;
    }
}